// round 8
// baseline (speedup 1.0000x reference)
#include <cuda_runtime.h>
#include <stdint.h>

// Problem constants (fixed by the reference generator).
#define HID    2048
#define BMAX   128
#define TSTEPS 128
#define MAXTOT (BMAX * TSTEPS)

// GEMM tiling: CTA tile 128(M) x 32(N) x 32(K), 256 threads,
// warps arranged 4(M) x 2(N), warp tile 32x16, mma.sync m16n8k8 tf32.
#define MTILE 128
#define NTILE 32
#define KTILE 32
#define KPAD  (KTILE + 4)

// Scratch (allocation-free rule: device globals only).
__device__ float g_pre[(size_t)MAXTOT * HID];   // x @ W_ih^T + (b_ih + b_hh), packed rows
__device__ float g_h[2][BMAX * HID];            // ping-pong hidden state (fp32)
__device__ float g_bias[HID];                   // b_ih + b_hh
__device__ int   g_bsps[TSTEPS];
__device__ int   g_offs[TSTEPS];                // exclusive prefix sum of bsps

// ---------------------------------------------------------------------------
// helpers
// ---------------------------------------------------------------------------
__device__ __forceinline__ float f2tf(float x) {
    uint32_t u;
    asm("cvt.rna.tf32.f32 %0, %1;" : "=r"(u) : "f"(x));
    return __uint_as_float(u);
}
__device__ __forceinline__ float4 f2tf4(float4 v) {
    v.x = f2tf(v.x); v.y = f2tf(v.y); v.z = f2tf(v.z); v.w = f2tf(v.w);
    return v;
}
__device__ __forceinline__ void mma8(float d[4], const uint32_t a[4], const uint32_t b[2]) {
    asm volatile(
        "mma.sync.aligned.m16n8k8.row.col.f32.tf32.tf32.f32 "
        "{%0,%1,%2,%3}, {%4,%5,%6,%7}, {%8,%9}, {%0,%1,%2,%3};"
        : "+f"(d[0]), "+f"(d[1]), "+f"(d[2]), "+f"(d[3])
        : "r"(a[0]), "r"(a[1]), "r"(a[2]), "r"(a[3]),
          "r"(b[0]), "r"(b[1]));
}

// ---------------------------------------------------------------------------
// setup: parse bsps (int32 OR int64 — detected on device), prefix sums,
// bias sum, init hidden state buffers and the h_final output region.
// ---------------------------------------------------------------------------
__global__ void k_setup(const uint32_t* __restrict__ bsps_w, int nelem,
                        const float* __restrict__ hidden,
                        const float* __restrict__ bih,
                        const float* __restrict__ bhh,
                        float* __restrict__ out_h) {
    const int tid = threadIdx.x;
    if (tid == 0) {
        // all bsps values are >= 1, so for little-endian int64 word[1]==0.
        const bool is64 = (nelem >= 2) && (bsps_w[1] == 0u);
        int off = 0;
        for (int t = 0; t < TSTEPS; ++t) {
            int v = (int)bsps_w[is64 ? 2 * t : t];
            g_bsps[t] = v;
            g_offs[t] = off;
            off += v;
        }
    }
    for (int n = tid; n < HID; n += blockDim.x) g_bias[n] = bih[n] + bhh[n];

    const float4* hv = (const float4*)hidden;
    float4* h0 = (float4*)g_h[0];
    float4* ho = (float4*)out_h;   // h_final region of d_out
    for (int i = tid; i < BMAX * HID / 4; i += blockDim.x) {
        float4 v = hv[i];
        h0[i] = v;
        ho[i] = v;
    }
}

// ---------------------------------------------------------------------------
// Kernel A: g_pre[r, n] = sum_k x[r,k] * W_ih[n,k] + bias[n]   (tf32 mma)
// grid = (HID/NTILE, ceil(Mtot/MTILE)), 256 threads
// ---------------------------------------------------------------------------
__global__ void __launch_bounds__(256, 1)
k_pre(const float* __restrict__ X, const float* __restrict__ W, int Mtot) {
    __shared__ float As[MTILE][KPAD];
    __shared__ float Bs[NTILE][KPAD];

    const int tid  = threadIdx.x;
    const int m0   = blockIdx.y * MTILE;
    const int n0   = blockIdx.x * NTILE;
    const int lane = tid & 31;
    const int g    = lane >> 2, tg = lane & 3;
    const int warp = tid >> 5;
    const int wm0  = (warp & 3) * 32;
    const int wn0  = (warp >> 2) * 16;

    int aRow[4], aC4[4];
#pragma unroll
    for (int i = 0; i < 4; i++) { int lin = tid + i * 256; aRow[i] = lin >> 3; aC4[i] = lin & 7; }
    const int bRow = tid >> 3, bC4 = tid & 7;

    const float* Aptr[4];
#pragma unroll
    for (int i = 0; i < 4; i++) {
        int gr = m0 + aRow[i];
        if (gr >= Mtot) gr = Mtot - 1;   // clamp; store is guarded
        Aptr[i] = X + (size_t)gr * HID + aC4[i] * 4;
    }
    const float* Bptr = W + (size_t)(n0 + bRow) * HID + bC4 * 4;

    float4 pa[4], pb;
#pragma unroll
    for (int i = 0; i < 4; i++) pa[i] = *(const float4*)(Aptr[i]);
    pb = *(const float4*)(Bptr);

    float acc[2][2][4];
#pragma unroll
    for (int i = 0; i < 2; i++)
#pragma unroll
        for (int j = 0; j < 2; j++)
#pragma unroll
            for (int q = 0; q < 4; q++) acc[i][j][q] = 0.f;

    for (int k0 = 0; k0 < HID; k0 += KTILE) {
#pragma unroll
        for (int i = 0; i < 4; i++) *(float4*)&As[aRow[i]][aC4[i] * 4] = f2tf4(pa[i]);
        *(float4*)&Bs[bRow][bC4 * 4] = f2tf4(pb);
        __syncthreads();
        if (k0 + KTILE < HID) {    // prefetch next tile (overlaps with compute)
#pragma unroll
            for (int i = 0; i < 4; i++) pa[i] = *(const float4*)(Aptr[i] + k0 + KTILE);
            pb = *(const float4*)(Bptr + k0 + KTILE);
        }
#pragma unroll
        for (int ks = 0; ks < 4; ks++) {
            const int kk = ks * 8;
            uint32_t a[2][4], b[2][2];
#pragma unroll
            for (int mi = 0; mi < 2; mi++) {
                const int m = wm0 + mi * 16 + g;
                a[mi][0] = __float_as_uint(As[m    ][kk + tg    ]);
                a[mi][1] = __float_as_uint(As[m + 8][kk + tg    ]);
                a[mi][2] = __float_as_uint(As[m    ][kk + tg + 4]);
                a[mi][3] = __float_as_uint(As[m + 8][kk + tg + 4]);
            }
#pragma unroll
            for (int ni = 0; ni < 2; ni++) {
                const int n = wn0 + ni * 8 + g;
                b[ni][0] = __float_as_uint(Bs[n][kk + tg    ]);
                b[ni][1] = __float_as_uint(Bs[n][kk + tg + 4]);
            }
#pragma unroll
            for (int mi = 0; mi < 2; mi++)
#pragma unroll
                for (int ni = 0; ni < 2; ni++)
                    mma8(acc[mi][ni], a[mi], b[ni]);
        }
        __syncthreads();
    }

#pragma unroll
    for (int mi = 0; mi < 2; mi++)
#pragma unroll
        for (int ni = 0; ni < 2; ni++)
#pragma unroll
            for (int h = 0; h < 2; h++) {
                const int r = m0 + wm0 + mi * 16 + g + h * 8;
                const int c = n0 + wn0 + ni * 8 + tg * 2;
                if (r < Mtot) {
                    float2 v;
                    v.x = acc[mi][ni][h * 2 + 0] + g_bias[c];
                    v.y = acc[mi][ni][h * 2 + 1] + g_bias[c + 1];
                    *(float2*)&g_pre[(size_t)r * HID + c] = v;
                }
            }
}

// ---------------------------------------------------------------------------
// Kernel B (one per timestep): for rows m < bsps[t]:
//   hn = tanh(g_pre[offs[t]+m, :] + h_src @ W_hh^T)
//   write hn -> h_dst, packed output, h_final; rows >= bsps copy h forward.
// grid = HID/NTILE = 64 CTAs, 256 threads
// ---------------------------------------------------------------------------
__global__ void __launch_bounds__(256, 1)
k_step(const float* __restrict__ W, float* __restrict__ dout, int t, int src) {
    __shared__ float As[MTILE][KPAD];
    __shared__ float Bs[NTILE][KPAD];

    const float* __restrict__ H  = g_h[src];
    float* __restrict__       Hd = g_h[src ^ 1];
    const int bsp = g_bsps[t];
    const int off = g_offs[t];

    const int tid  = threadIdx.x;
    const int n0   = blockIdx.x * NTILE;
    const int lane = tid & 31;
    const int g    = lane >> 2, tg = lane & 3;
    const int warp = tid >> 5;
    const int wm0  = (warp & 3) * 32;
    const int wn0  = (warp >> 2) * 16;

    int aRow[4], aC4[4];
#pragma unroll
    for (int i = 0; i < 4; i++) { int lin = tid + i * 256; aRow[i] = lin >> 3; aC4[i] = lin & 7; }
    const int bRow = tid >> 3, bC4 = tid & 7;

    const float* Aptr[4];
#pragma unroll
    for (int i = 0; i < 4; i++) Aptr[i] = H + (size_t)aRow[i] * HID + aC4[i] * 4;
    const float* Bptr = W + (size_t)(n0 + bRow) * HID + bC4 * 4;

    float4 pa[4], pb;
#pragma unroll
    for (int i = 0; i < 4; i++) pa[i] = *(const float4*)(Aptr[i]);
    pb = *(const float4*)(Bptr);

    float acc[2][2][4];
#pragma unroll
    for (int i = 0; i < 2; i++)
#pragma unroll
        for (int j = 0; j < 2; j++)
#pragma unroll
            for (int q = 0; q < 4; q++) acc[i][j][q] = 0.f;

    for (int k0 = 0; k0 < HID; k0 += KTILE) {
#pragma unroll
        for (int i = 0; i < 4; i++) *(float4*)&As[aRow[i]][aC4[i] * 4] = f2tf4(pa[i]);
        *(float4*)&Bs[bRow][bC4 * 4] = f2tf4(pb);
        __syncthreads();
        if (k0 + KTILE < HID) {
#pragma unroll
            for (int i = 0; i < 4; i++) pa[i] = *(const float4*)(Aptr[i] + k0 + KTILE);
            pb = *(const float4*)(Bptr + k0 + KTILE);
        }
#pragma unroll
        for (int ks = 0; ks < 4; ks++) {
            const int kk = ks * 8;
            uint32_t a[2][4], b[2][2];
#pragma unroll
            for (int mi = 0; mi < 2; mi++) {
                const int m = wm0 + mi * 16 + g;
                a[mi][0] = __float_as_uint(As[m    ][kk + tg    ]);
                a[mi][1] = __float_as_uint(As[m + 8][kk + tg    ]);
                a[mi][2] = __float_as_uint(As[m    ][kk + tg + 4]);
                a[mi][3] = __float_as_uint(As[m + 8][kk + tg + 4]);
            }
#pragma unroll
            for (int ni = 0; ni < 2; ni++) {
                const int n = wn0 + ni * 8 + g;
                b[ni][0] = __float_as_uint(Bs[n][kk + tg    ]);
                b[ni][1] = __float_as_uint(Bs[n][kk + tg + 4]);
            }
#pragma unroll
            for (int mi = 0; mi < 2; mi++)
#pragma unroll
                for (int ni = 0; ni < 2; ni++)
                    mma8(acc[mi][ni], a[mi], b[ni]);
        }
        __syncthreads();
    }

    // epilogue: tanh + masked update + packed output + running h_final
#pragma unroll
    for (int mi = 0; mi < 2; mi++)
#pragma unroll
        for (int ni = 0; ni < 2; ni++)
#pragma unroll
            for (int h = 0; h < 2; h++) {
                const int r = wm0 + mi * 16 + g + h * 8;       // 0..127
                const int c = n0 + wn0 + ni * 8 + tg * 2;
                float2 v;
                if (r < bsp) {
                    const size_t prow = (size_t)(off + r) * HID + c;
                    v.x = tanhf(acc[mi][ni][h * 2 + 0] + g_pre[prow]);
                    v.y = tanhf(acc[mi][ni][h * 2 + 1] + g_pre[prow + 1]);
                    *(float2*)&dout[(size_t)BMAX * HID + prow] = v;   // packed output
                    *(float2*)&dout[(size_t)r * HID + c]       = v;   // h_final (last active write wins)
                } else {
                    v = *(const float2*)&H[(size_t)r * HID + c];      // freeze finished sequence
                }
                *(float2*)&Hd[(size_t)r * HID + c] = v;
            }
}

// ---------------------------------------------------------------------------
// launch
// ---------------------------------------------------------------------------
extern "C" void kernel_launch(void* const* d_in, const int* in_sizes, int n_in,
                              void* d_out, int out_size) {
    const float*    x    = (const float*)d_in[0];
    const float*    hid  = (const float*)d_in[1];
    const float*    Wih  = (const float*)d_in[2];
    const float*    Whh  = (const float*)d_in[3];
    const float*    bih  = (const float*)d_in[4];
    const float*    bhh  = (const float*)d_in[5];
    const uint32_t* bsps = (const uint32_t*)d_in[6];
    float*          out  = (float*)d_out;

    int total = in_sizes[0] / HID;
    if (total > MAXTOT) total = MAXTOT;

    k_setup<<<1, 256>>>(bsps, in_sizes[6], hid, bih, bhh, out);

    const int mt = (total + MTILE - 1) / MTILE;
    k_pre<<<dim3(HID / NTILE, mt), 256>>>(x, Wih, total);

    for (int t = 0; t < TSTEPS; ++t)
        k_step<<<HID / NTILE, 256>>>(Whh, out, t, t & 1);
}